// round 9
// baseline (speedup 1.0000x reference)
#include <cuda_runtime.h>

// Problem constants
#define NBATCH   512
#define DD       64          // state dim
#define WIDTH    128         // MLP width
#define SSEG     120         // steps per delay segment
#define NSTEPS   600
#define NSAVE    601
#define XDIM     129         // 2*D + 1
#define XP       144         // padded stride: four 36-float quarters / eight 18-float eighths
#define QUARX    36          // floats per quarter (L1/L2 split)
#define EGTX     18          // floats per eighth (L3 split)
#define NCHQ     9           // float4 chunks per quarter
#define NCHE     9           // ulonglong (2-float) chunks per eighth
#define BT       4           // batch rows per block
#define NTHREADS 512
#define NBLOCKS  (NBATCH / BT)   // 128

// Dopri5 tableau (stage j uses AC[j][0..j-1]); CH = both c_i (time offsets) and
// history interpolation coefficient; BCOEF = solution weights.
__constant__ float AC[6][5] = {
    {0.f, 0.f, 0.f, 0.f, 0.f},
    {0.2f, 0.f, 0.f, 0.f, 0.f},
    {(float)(3.0/40.0), (float)(9.0/40.0), 0.f, 0.f, 0.f},
    {(float)(44.0/45.0), (float)(-56.0/15.0), (float)(32.0/9.0), 0.f, 0.f},
    {(float)(19372.0/6561.0), (float)(-25360.0/2187.0), (float)(64448.0/6561.0),
     (float)(-212.0/729.0), 0.f},
    {(float)(9017.0/3168.0), (float)(-355.0/33.0), (float)(46732.0/5247.0),
     (float)(49.0/176.0), (float)(-5103.0/18656.0)}
};
__constant__ float CH[6] = {0.f, 0.2f, 0.3f, 0.8f, (float)(8.0/9.0), 1.0f};
__constant__ float BCOEF[6] = {(float)(35.0/384.0), 0.f, (float)(500.0/1113.0),
                               (float)(125.0/192.0), (float)(-2187.0/6784.0),
                               (float)(11.0/84.0)};

// ---- packed fp32x2 helpers: FFMA2 lanes = even/odd input partial sums ----
__device__ __forceinline__ void fma2(unsigned long long& acc,
                                     unsigned long long w2,
                                     unsigned long long x2) {
    asm("fma.rn.f32x2 %0, %1, %2, %0;" : "+l"(acc) : "l"(w2), "l"(x2));
}
__device__ __forceinline__ unsigned long long pkf2(float a, float b) {
    unsigned long long r;
    asm("mov.b64 %0, {%1, %2};" : "=l"(r) : "f"(a), "f"(b));
    return r;
}
__device__ __forceinline__ float red2(unsigned long long v) {
    float2 r;
    asm("mov.b64 {%0, %1}, %2;" : "=f"(r.x), "=f"(r.y) : "l"(v));
    return r.x + r.y;
}
__device__ __forceinline__ float shx(float v, int m) {
    return __shfl_xor_sync(0xffffffffu, v, m);
}

// WID layer (L1/L2), 512 threads: thread (j = tid>>2, q = tid&3) holds the q-th
// 36-float quarter of weight row j in registers (9 ulonglong2 = 36 regs). Only
// broadcast x loads (4 distinct addresses/warp, conflict-free) touch SMEM.
// shfl_xor(1)+shfl_xor(2) combine the 4 K-quarters.
__device__ __forceinline__ void layer_wid_reg(const ulonglong2* __restrict__ wr,
                                              float bias,
                                              const float* __restrict__ xin,
                                              float* __restrict__ xout,
                                              int j, int q) {
    unsigned long long a0 = 0ull, a1 = 0ull, a2 = 0ull, a3 = 0ull;
    const ulonglong2* x0 = reinterpret_cast<const ulonglong2*>(xin + 0 * XP + q * QUARX);
    const ulonglong2* x1 = reinterpret_cast<const ulonglong2*>(xin + 1 * XP + q * QUARX);
    const ulonglong2* x2 = reinterpret_cast<const ulonglong2*>(xin + 2 * XP + q * QUARX);
    const ulonglong2* x3 = reinterpret_cast<const ulonglong2*>(xin + 3 * XP + q * QUARX);
#pragma unroll
    for (int c = 0; c < NCHQ; ++c) {
        ulonglong2 w = wr[c];
        ulonglong2 p0 = x0[c]; fma2(a0, w.x, p0.x); fma2(a0, w.y, p0.y);
        ulonglong2 p1 = x1[c]; fma2(a1, w.x, p1.x); fma2(a1, w.y, p1.y);
        ulonglong2 p2 = x2[c]; fma2(a2, w.x, p2.x); fma2(a2, w.y, p2.y);
        ulonglong2 p3 = x3[c]; fma2(a3, w.x, p3.x); fma2(a3, w.y, p3.y);
    }
    float s0 = red2(a0), s1 = red2(a1), s2 = red2(a2), s3 = red2(a3);
    s0 += shx(s0, 1); s0 += shx(s0, 2);
    s1 += shx(s1, 1); s1 += shx(s1, 2);
    s2 += shx(s2, 1); s2 += shx(s2, 2);
    s3 += shx(s3, 1); s3 += shx(s3, 2);
    if (q == 0) {
        xout[0 * XP + j] = fmaxf(s0 + bias, 0.f);
        xout[1 * XP + j] = fmaxf(s1 + bias, 0.f);
        xout[2 * XP + j] = fmaxf(s2 + bias, 0.f);
        xout[3 * XP + j] = fmaxf(s3 + bias, 0.f);
    }
}

// Output layer (L3), 512 threads: thread (jq = tid>>3, e = tid&7) holds the
// e-th 18-float eighth of W3 row jq (9 ulonglong = 18 regs). 8-wide shuffle
// reduction (xor 1,2,4). No relu. Writes k[4][64].
__device__ __forceinline__ void layer_out_reg(const unsigned long long* __restrict__ wr,
                                              float bias,
                                              const float* __restrict__ xin,
                                              float* __restrict__ kout,
                                              int jq, int e) {
    unsigned long long a0 = 0ull, a1 = 0ull, a2 = 0ull, a3 = 0ull;
    const unsigned long long* x0 = reinterpret_cast<const unsigned long long*>(xin + 0 * XP + e * EGTX);
    const unsigned long long* x1 = reinterpret_cast<const unsigned long long*>(xin + 1 * XP + e * EGTX);
    const unsigned long long* x2 = reinterpret_cast<const unsigned long long*>(xin + 2 * XP + e * EGTX);
    const unsigned long long* x3 = reinterpret_cast<const unsigned long long*>(xin + 3 * XP + e * EGTX);
#pragma unroll
    for (int c = 0; c < NCHE; ++c) {
        unsigned long long w = wr[c];
        fma2(a0, w, x0[c]);
        fma2(a1, w, x1[c]);
        fma2(a2, w, x2[c]);
        fma2(a3, w, x3[c]);
    }
    float s0 = red2(a0), s1 = red2(a1), s2 = red2(a2), s3 = red2(a3);
    s0 += shx(s0, 1); s0 += shx(s0, 2); s0 += shx(s0, 4);
    s1 += shx(s1, 1); s1 += shx(s1, 2); s1 += shx(s1, 4);
    s2 += shx(s2, 1); s2 += shx(s2, 2); s2 += shx(s2, 4);
    s3 += shx(s3, 1); s3 += shx(s3, 2); s3 += shx(s3, 4);
    if (e == 0) {
        kout[0 * DD + jq] = s0 + bias;
        kout[1 * DD + jq] = s1 + bias;
        kout[2 * DD + jq] = s2 + bias;
        kout[3 * DD + jq] = s3 + bias;
    }
}

// Build stage input x = [y_stage, hist, t], plain layout [BT][XP].
__device__ __forceinline__ void build_x(float* __restrict__ sx,
                                        const float* __restrict__ sy,
                                        const float* __restrict__ sk,
                                        int st, float chist,
                                        const float* __restrict__ yp0,
                                        const float* __restrict__ yp1,
                                        float tval, float dtv, int tid) {
    for (int slot = tid; slot < BT * XDIM; slot += NTHREADS) {
        int r = slot / XDIM;
        int i = slot - r * XDIM;
        float v;
        if (i < DD) {
            float s = 0.f;
            for (int jj = 0; jj < st; ++jj)
                s += AC[st][jj] * sk[jj * BT * DD + r * DD + i];
            v = sy[r * DD + i] + dtv * s;
        } else if (i < 2 * DD) {
            int d = i - DD;
            float p0 = yp0[r * DD + d], p1 = yp1[r * DD + d];
            v = p0 + chist * (p1 - p0);
        } else {
            v = tval;
        }
        sx[r * XP + i] = v;
    }
}

extern __shared__ float smem[];

__global__ __launch_bounds__(NTHREADS, 1)
void dde_kernel(const float* __restrict__ ts, const float* __restrict__ y0,
                const float* __restrict__ W1, const float* __restrict__ b1,
                const float* __restrict__ W2, const float* __restrict__ b2,
                const float* __restrict__ W3, const float* __restrict__ b3,
                float* __restrict__ out, long long out_size) {
    // SMEM layout (floats) — activations + state only (~4.3K floats)
    float* sx  = smem;                        // BT*XP
    float* sh1 = sx + BT * XP;                // BT*XP
    float* sh2 = sh1 + BT * XP;               // BT*XP
    float* sk  = sh2 + BT * XP;               // 6*BT*DD
    float* sy  = sk + 6 * BT * DD;            // BT*DD
    float* sy0 = sy + BT * DD;                // BT*DD
    float* syp0 = sy0 + BT * DD;              // BT*DD
    float* syp1 = syp0 + BT * DD;             // BT*DD

    const int tid = threadIdx.x;
    const int b0 = blockIdx.x * BT;
    const int j  = tid >> 2;       // L1/L2 output (0..127)
    const int q  = tid & 3;        // K-quarter
    const int jq = tid >> 3;       // L3 output (0..63)
    const int e  = tid & 7;        // K-eighth

    // ---- Load weights into REGISTERS (persist across all 600 steps) ----
    ulonglong2 w1r[NCHQ], w2r[NCHQ];
    unsigned long long w3r[NCHE];
#pragma unroll
    for (int c = 0; c < NCHQ; ++c) {
        int base = q * QUARX + 4 * c;
        float f0 = (base + 0 < XDIM) ? W1[j * XDIM + base + 0] : 0.f;
        float f1 = (base + 1 < XDIM) ? W1[j * XDIM + base + 1] : 0.f;
        float f2 = (base + 2 < XDIM) ? W1[j * XDIM + base + 2] : 0.f;
        float f3 = (base + 3 < XDIM) ? W1[j * XDIM + base + 3] : 0.f;
        w1r[c] = make_ulonglong2(pkf2(f0, f1), pkf2(f2, f3));
        float g0 = (base + 0 < WIDTH) ? W2[j * WIDTH + base + 0] : 0.f;
        float g1 = (base + 1 < WIDTH) ? W2[j * WIDTH + base + 1] : 0.f;
        float g2 = (base + 2 < WIDTH) ? W2[j * WIDTH + base + 2] : 0.f;
        float g3 = (base + 3 < WIDTH) ? W2[j * WIDTH + base + 3] : 0.f;
        w2r[c] = make_ulonglong2(pkf2(g0, g1), pkf2(g2, g3));
    }
#pragma unroll
    for (int c = 0; c < NCHE; ++c) {
        int base = e * EGTX + 2 * c;
        float f0 = (base + 0 < WIDTH) ? W3[jq * WIDTH + base + 0] : 0.f;
        float f1 = (base + 1 < WIDTH) ? W3[jq * WIDTH + base + 1] : 0.f;
        w3r[c] = pkf2(f0, f1);
    }
    const float bj1 = b1[j];
    const float bj2 = b2[j];
    const float bj3 = b3[jq];

    // Zero activation buffers (pads 129..143 stay 0 forever: build_x writes
    // i<129, layers write col<128, so pad contributions are exactly 0).
    for (int i = tid; i < 3 * BT * XP; i += NTHREADS) sx[i] = 0.f;

    // Initial state + write ys[:,0,:] = y0.
    for (int idx = tid; idx < BT * DD; idx += NTHREADS) {
        int r = idx >> 6, d = idx & 63;
        float v = y0[(size_t)(b0 + r) * DD + d];
        sy[idx] = v;
        sy0[idx] = v;
        out[(size_t)(b0 + r) * NSAVE * DD + d] = v;
    }
    const float ts0 = ts[0];
    const float dtv = ts[1] - ts[0];
    __syncthreads();

#pragma unroll 1
    for (int step = 0; step < NSTEPS; ++step) {
        const float* yp0;
        const float* yp1;
        if (step < SSEG) {
            yp0 = sy0;
            yp1 = sy0;   // constant-history segment: y(t-tau) = y0
        } else {
            // Dense-output lookup: previous-segment grid points step-S, step-S+1
            // (written by this block >=119 steps ago; __syncthreads gives visibility).
            if (tid < 128) {
                int sel = tid >> 6;       // 0 -> yp0, 1 -> yp1
                int idx = tid & 63;       // float4 slot within [BT][DD]
                int r = idx >> 4, d4 = idx & 15;
                const float4* src = reinterpret_cast<const float4*>(
                    out + (size_t)(b0 + r) * NSAVE * DD + (size_t)(step - SSEG + sel) * DD)
                    + d4;
                float4 v = *src;
                float4* dst = reinterpret_cast<float4*>(sel ? syp1 : syp0);
                dst[idx] = v;
            }
            yp0 = syp0;
            yp1 = syp1;
            __syncthreads();
        }
        const float tbase = ts0 + (float)step * dtv;

#pragma unroll 1
        for (int st = 0; st < 6; ++st) {
            build_x(sx, sy, sk, st, CH[st], yp0, yp1, tbase + CH[st] * dtv, dtv, tid);
            __syncthreads();
            layer_wid_reg(w1r, bj1, sx, sh1, j, q);
            __syncthreads();
            layer_wid_reg(w2r, bj2, sh1, sh2, j, q);
            __syncthreads();
            layer_out_reg(w3r, bj3, sh2, sk + st * BT * DD, jq, e);
            __syncthreads();
        }

        // y_{n+1} = y_n + dt * sum_j b_j k_j ; write dense output.
        if (tid < BT * DD) {
            int ee = tid;
            float acc = 0.f;
#pragma unroll
            for (int jj = 0; jj < 6; ++jj) acc += BCOEF[jj] * sk[jj * BT * DD + ee];
            float yn = sy[ee] + dtv * acc;
            sy[ee] = yn;
            int r = ee >> 6, d = ee & 63;
            out[(size_t)(b0 + r) * NSAVE * DD + (size_t)(step + 1) * DD + d] = yn;
        }
        __syncthreads();
    }

    // num_steps (int 600 cast to output dtype) appended after ys.
    if (blockIdx.x == 0) {
        long long yssz = (long long)NBATCH * NSAVE * DD;
        for (long long i = yssz + tid; i < out_size; i += NTHREADS) out[i] = 600.0f;
    }
}

#define SMEM_FLOATS (3 * BT * XP + 6 * BT * DD + 4 * BT * DD)

extern "C" void kernel_launch(void* const* d_in, const int* in_sizes, int n_in,
                              void* d_out, int out_size) {
    const float* ts = (const float*)d_in[0];
    const float* y0 = (const float*)d_in[1];
    const float* W1 = (const float*)d_in[2];
    const float* b1 = (const float*)d_in[3];
    const float* W2 = (const float*)d_in[4];
    const float* b2 = (const float*)d_in[5];
    const float* W3 = (const float*)d_in[6];
    const float* b3 = (const float*)d_in[7];
    float* out = (float*)d_out;

    size_t smem_bytes = (size_t)SMEM_FLOATS * sizeof(float);
    cudaFuncSetAttribute(dde_kernel, cudaFuncAttributeMaxDynamicSharedMemorySize,
                         (int)smem_bytes);

    dde_kernel<<<NBLOCKS, NTHREADS, smem_bytes>>>(ts, y0, W1, b1, W2, b2, W3, b3,
                                                  out, (long long)out_size);
}

// round 15
// speedup vs baseline: 1.7830x; 1.7830x over previous
#include <cuda_runtime.h>

// Problem constants
#define NBATCH   512
#define DD       64          // state dim
#define WIDTH    128         // MLP width
#define SSEG     120         // steps per delay segment
#define NSTEPS   600
#define NSAVE    601
#define XDIM     129         // 2*D + 1
#define XP       144         // padded stride: four 36-float K-quarters
#define QW       36          // floats per K-quarter (L1/L2)
#define NCQ      9           // float4 chunks per quarter (L1/L2)
#define E3W      16          // floats per K-eighth (L3)
#define NC3      4           // float4 chunks per eighth (L3)
#define BT       4           // batch rows per block
#define NTHREADS 512
#define NBLOCKS  (NBATCH / BT)   // 128

// Dopri5 tableau (stage j uses AC[j][0..j-1]); CH = both c_i (time offsets) and
// history interpolation coefficient; BCOEF = solution weights.
__constant__ float AC[6][5] = {
    {0.f, 0.f, 0.f, 0.f, 0.f},
    {0.2f, 0.f, 0.f, 0.f, 0.f},
    {(float)(3.0/40.0), (float)(9.0/40.0), 0.f, 0.f, 0.f},
    {(float)(44.0/45.0), (float)(-56.0/15.0), (float)(32.0/9.0), 0.f, 0.f},
    {(float)(19372.0/6561.0), (float)(-25360.0/2187.0), (float)(64448.0/6561.0),
     (float)(-212.0/729.0), 0.f},
    {(float)(9017.0/3168.0), (float)(-355.0/33.0), (float)(46732.0/5247.0),
     (float)(49.0/176.0), (float)(-5103.0/18656.0)}
};
__constant__ float CH[6] = {0.f, 0.2f, 0.3f, 0.8f, (float)(8.0/9.0), 1.0f};
__constant__ float BCOEF[6] = {(float)(35.0/384.0), 0.f, (float)(500.0/1113.0),
                               (float)(125.0/192.0), (float)(-2187.0/6784.0),
                               (float)(11.0/84.0)};

// ---- packed fp32x2 helpers: FFMA2 lanes = even/odd input partial sums ----
__device__ __forceinline__ void fma2(unsigned long long& acc,
                                     unsigned long long w2,
                                     unsigned long long x2) {
    asm("fma.rn.f32x2 %0, %1, %2, %0;" : "+l"(acc) : "l"(w2), "l"(x2));
}
__device__ __forceinline__ unsigned long long pkf2(float a, float b) {
    unsigned long long r;
    asm("mov.b64 %0, {%1, %2};" : "=l"(r) : "f"(a), "f"(b));
    return r;
}
__device__ __forceinline__ float red2(unsigned long long v) {
    float2 r;
    asm("mov.b64 {%0, %1}, %2;" : "=f"(r.x), "=f"(r.y) : "l"(v));
    return r.x + r.y;
}

// L1/L2 partial: warp w serves K-quarter q4=w>>2; lane computes output
// j=(w&3)*32+lane for all 4 batch rows. Every x load: ALL 32 lanes read the
// SAME address -> exactly 1 wavefront per LDS. Partials go to spart[q4][r][j].
__device__ __forceinline__ void layer_wid_part(const ulonglong2* __restrict__ wr,
                                               const float* __restrict__ xin,
                                               float* __restrict__ spart,
                                               int j, int q4) {
    unsigned long long a0 = 0ull, a1 = 0ull, a2 = 0ull, a3 = 0ull;
    const ulonglong2* x0 = reinterpret_cast<const ulonglong2*>(xin + 0 * XP + q4 * QW);
    const ulonglong2* x1 = reinterpret_cast<const ulonglong2*>(xin + 1 * XP + q4 * QW);
    const ulonglong2* x2 = reinterpret_cast<const ulonglong2*>(xin + 2 * XP + q4 * QW);
    const ulonglong2* x3 = reinterpret_cast<const ulonglong2*>(xin + 3 * XP + q4 * QW);
#pragma unroll
    for (int c = 0; c < NCQ; ++c) {
        ulonglong2 w = wr[c];
        ulonglong2 p0 = x0[c]; fma2(a0, w.x, p0.x); fma2(a0, w.y, p0.y);
        ulonglong2 p1 = x1[c]; fma2(a1, w.x, p1.x); fma2(a1, w.y, p1.y);
        ulonglong2 p2 = x2[c]; fma2(a2, w.x, p2.x); fma2(a2, w.y, p2.y);
        ulonglong2 p3 = x3[c]; fma2(a3, w.x, p3.x); fma2(a3, w.y, p3.y);
    }
    float* dst = spart + q4 * (BT * WIDTH) + j;
    dst[0 * WIDTH] = red2(a0);
    dst[1 * WIDTH] = red2(a1);
    dst[2 * WIDTH] = red2(a2);
    dst[3 * WIDTH] = red2(a3);
}

// L1/L2 finalize: slot s=tid (512 = 4 rows x 128 outputs): sum 4 K-quarter
// partials + bias, relu, write activation row. Stride-1 SMEM, conflict-free.
__device__ __forceinline__ void layer_wid_fin(const float* __restrict__ spart,
                                              const float* __restrict__ sb,
                                              float* __restrict__ xout,
                                              int tid) {
    float v = spart[0 * (BT * WIDTH) + tid] + spart[1 * (BT * WIDTH) + tid]
            + spart[2 * (BT * WIDTH) + tid] + spart[3 * (BT * WIDTH) + tid];
    int r = tid >> 7, jx = tid & 127;
    xout[r * XP + jx] = fmaxf(v + sb[jx], 0.f);
}

// L3 partial: warp w: K-eighth e8=w>>1 (16 floats), output half hf=w&1,
// jq=hf*32+lane; computes all 4 rows. x loads single-address per warp.
// Weights: only 4 ulonglong2 = 8 regs. Partials to kpart[e8][r][jq].
__device__ __forceinline__ void layer_out_part(const ulonglong2* __restrict__ wr,
                                               const float* __restrict__ xin,
                                               float* __restrict__ kpart,
                                               int jq, int e8) {
    unsigned long long a0 = 0ull, a1 = 0ull, a2 = 0ull, a3 = 0ull;
    const ulonglong2* x0 = reinterpret_cast<const ulonglong2*>(xin + 0 * XP + e8 * E3W);
    const ulonglong2* x1 = reinterpret_cast<const ulonglong2*>(xin + 1 * XP + e8 * E3W);
    const ulonglong2* x2 = reinterpret_cast<const ulonglong2*>(xin + 2 * XP + e8 * E3W);
    const ulonglong2* x3 = reinterpret_cast<const ulonglong2*>(xin + 3 * XP + e8 * E3W);
#pragma unroll
    for (int c = 0; c < NC3; ++c) {
        ulonglong2 w = wr[c];
        ulonglong2 p0 = x0[c]; fma2(a0, w.x, p0.x); fma2(a0, w.y, p0.y);
        ulonglong2 p1 = x1[c]; fma2(a1, w.x, p1.x); fma2(a1, w.y, p1.y);
        ulonglong2 p2 = x2[c]; fma2(a2, w.x, p2.x); fma2(a2, w.y, p2.y);
        ulonglong2 p3 = x3[c]; fma2(a3, w.x, p3.x); fma2(a3, w.y, p3.y);
    }
    float* dst = kpart + e8 * (BT * DD) + jq;
    dst[0 * DD] = red2(a0);
    dst[1 * DD] = red2(a1);
    dst[2 * DD] = red2(a2);
    dst[3 * DD] = red2(a3);
}

// L3 finalize: slot s=tid<256 (4 rows x 64 outputs): sum 8 partials + bias.
__device__ __forceinline__ void layer_out_fin(const float* __restrict__ kpart,
                                              const float* __restrict__ sb3,
                                              float* __restrict__ kout,
                                              int tid) {
    if (tid < BT * DD) {
        float v = 0.f;
#pragma unroll
        for (int p = 0; p < 8; ++p) v += kpart[p * (BT * DD) + tid];
        kout[tid] = v + sb3[tid & 63];
    }
}

// Build stage input x = [y_stage, hist, t], plain layout [BT][XP].
__device__ __forceinline__ void build_x(float* __restrict__ sx,
                                        const float* __restrict__ sy,
                                        const float* __restrict__ sk,
                                        int st, float chist,
                                        const float* __restrict__ yp0,
                                        const float* __restrict__ yp1,
                                        float tval, float dtv, int tid) {
    for (int slot = tid; slot < BT * XDIM; slot += NTHREADS) {
        int r = slot / XDIM;
        int i = slot - r * XDIM;
        float v;
        if (i < DD) {
            float s = 0.f;
            for (int jj = 0; jj < st; ++jj)
                s += AC[st][jj] * sk[jj * BT * DD + r * DD + i];
            v = sy[r * DD + i] + dtv * s;
        } else if (i < 2 * DD) {
            int d = i - DD;
            float p0 = yp0[r * DD + d], p1 = yp1[r * DD + d];
            v = p0 + chist * (p1 - p0);
        } else {
            v = tval;
        }
        sx[r * XP + i] = v;
    }
}

extern __shared__ float smem[];

__global__ __launch_bounds__(NTHREADS, 1)
void dde_kernel(const float* __restrict__ ts, const float* __restrict__ y0,
                const float* __restrict__ W1, const float* __restrict__ b1,
                const float* __restrict__ W2, const float* __restrict__ b2,
                const float* __restrict__ W3, const float* __restrict__ b3,
                float* __restrict__ out, long long out_size) {
    // SMEM layout (floats)
    float* sx    = smem;                       // BT*XP
    float* sh1   = sx + BT * XP;               // BT*XP
    float* sh2   = sh1 + BT * XP;              // BT*XP
    float* sk    = sh2 + BT * XP;              // 6*BT*DD
    float* sy    = sk + 6 * BT * DD;           // BT*DD
    float* sy0   = sy + BT * DD;               // BT*DD
    float* syp0  = sy0 + BT * DD;              // BT*DD
    float* syp1  = syp0 + BT * DD;             // BT*DD
    float* spart = syp1 + BT * DD;             // 4*BT*WIDTH = 2048
    float* kpart = spart + 4 * BT * WIDTH;     // 8*BT*DD = 2048
    float* sb1   = kpart + 8 * BT * DD;        // WIDTH
    float* sb2   = sb1 + WIDTH;                // WIDTH
    float* sb3   = sb2 + WIDTH;                // DD

    const int tid = threadIdx.x;
    const int b0 = blockIdx.x * BT;
    const int w  = tid >> 5;
    const int l  = tid & 31;
    const int q4 = w >> 2;               // K-quarter (L1/L2)
    const int j  = (w & 3) * 32 + l;     // output 0..127 (L1/L2)
    const int e8 = w >> 1;               // K-eighth (L3)
    const int jq = (w & 1) * 32 + l;     // output 0..63 (L3)

    // ---- Weights into REGISTERS (persist across 600 steps; ~80 regs) ----
    ulonglong2 w1r[NCQ], w2r[NCQ], w3r[NC3];
#pragma unroll
    for (int c = 0; c < NCQ; ++c) {
        int base = q4 * QW + 4 * c;
        float f0 = (base + 0 < XDIM) ? W1[j * XDIM + base + 0] : 0.f;
        float f1 = (base + 1 < XDIM) ? W1[j * XDIM + base + 1] : 0.f;
        float f2 = (base + 2 < XDIM) ? W1[j * XDIM + base + 2] : 0.f;
        float f3 = (base + 3 < XDIM) ? W1[j * XDIM + base + 3] : 0.f;
        w1r[c] = make_ulonglong2(pkf2(f0, f1), pkf2(f2, f3));
        float g0 = (base + 0 < WIDTH) ? W2[j * WIDTH + base + 0] : 0.f;
        float g1 = (base + 1 < WIDTH) ? W2[j * WIDTH + base + 1] : 0.f;
        float g2 = (base + 2 < WIDTH) ? W2[j * WIDTH + base + 2] : 0.f;
        float g3 = (base + 3 < WIDTH) ? W2[j * WIDTH + base + 3] : 0.f;
        w2r[c] = make_ulonglong2(pkf2(g0, g1), pkf2(g2, g3));
    }
#pragma unroll
    for (int c = 0; c < NC3; ++c) {
        int base = e8 * E3W + 4 * c;     // always < 128
        w3r[c] = make_ulonglong2(pkf2(W3[jq * WIDTH + base + 0], W3[jq * WIDTH + base + 1]),
                                 pkf2(W3[jq * WIDTH + base + 2], W3[jq * WIDTH + base + 3]));
    }

    // Biases into SMEM; zero activation pads (129..143 stay 0 forever).
    for (int i = tid; i < 3 * BT * XP; i += NTHREADS) sx[i] = 0.f;
    if (tid < WIDTH) { sb1[tid] = b1[tid]; sb2[tid] = b2[tid]; }
    else if (tid < WIDTH + DD) { sb3[tid - WIDTH] = b3[tid - WIDTH]; }

    // Initial state + write ys[:,0,:] = y0.
    if (tid < BT * DD) {
        int r = tid >> 6, d = tid & 63;
        float v = y0[(size_t)(b0 + r) * DD + d];
        sy[tid] = v;
        sy0[tid] = v;
        out[(size_t)(b0 + r) * NSAVE * DD + d] = v;
    }
    const float ts0 = ts[0];
    const float dtv = ts[1] - ts[0];
    __syncthreads();

#pragma unroll 1
    for (int step = 0; step < NSTEPS; ++step) {
        const float* yp0;
        const float* yp1;
        if (step < SSEG) {
            yp0 = sy0;
            yp1 = sy0;   // constant-history segment: y(t-tau) = y0
        } else {
            // Dense-output lookup: previous-segment grid points step-S, step-S+1
            // (written by this block >=119 steps ago; __syncthreads gives visibility).
            if (tid < 128) {
                int sel = tid >> 6;       // 0 -> yp0, 1 -> yp1
                int idx = tid & 63;       // float4 slot within [BT][DD]
                int r = idx >> 4, d4 = idx & 15;
                const float4* src = reinterpret_cast<const float4*>(
                    out + (size_t)(b0 + r) * NSAVE * DD + (size_t)(step - SSEG + sel) * DD)
                    + d4;
                float4 v = *src;
                float4* dst = reinterpret_cast<float4*>(sel ? syp1 : syp0);
                dst[idx] = v;
            }
            yp0 = syp0;
            yp1 = syp1;
            __syncthreads();
        }
        const float tbase = ts0 + (float)step * dtv;

#pragma unroll 1
        for (int st = 0; st < 6; ++st) {
            build_x(sx, sy, sk, st, CH[st], yp0, yp1, tbase + CH[st] * dtv, dtv, tid);
            __syncthreads();
            layer_wid_part(w1r, sx, spart, j, q4);
            __syncthreads();
            layer_wid_fin(spart, sb1, sh1, tid);
            __syncthreads();
            layer_wid_part(w2r, sh1, spart, j, q4);
            __syncthreads();
            layer_wid_fin(spart, sb2, sh2, tid);
            __syncthreads();
            layer_out_part(w3r, sh2, kpart, jq, e8);
            __syncthreads();
            layer_out_fin(kpart, sb3, sk + st * BT * DD, tid);
            __syncthreads();
        }

        // y_{n+1} = y_n + dt * sum_j b_j k_j ; write dense output.
        if (tid < BT * DD) {
            float acc = 0.f;
#pragma unroll
            for (int jj = 0; jj < 6; ++jj) acc += BCOEF[jj] * sk[jj * BT * DD + tid];
            float yn = sy[tid] + dtv * acc;
            sy[tid] = yn;
            int r = tid >> 6, d = tid & 63;
            out[(size_t)(b0 + r) * NSAVE * DD + (size_t)(step + 1) * DD + d] = yn;
        }
        __syncthreads();
    }

    // num_steps (int 600 cast to output dtype) appended after ys.
    if (blockIdx.x == 0) {
        long long yssz = (long long)NBATCH * NSAVE * DD;
        for (long long i = yssz + tid; i < out_size; i += NTHREADS) out[i] = 600.0f;
    }
}

#define SMEM_FLOATS (3 * BT * XP + 6 * BT * DD + 4 * BT * DD \
                     + 4 * BT * WIDTH + 8 * BT * DD + 2 * WIDTH + DD)

extern "C" void kernel_launch(void* const* d_in, const int* in_sizes, int n_in,
                              void* d_out, int out_size) {
    const float* ts = (const float*)d_in[0];
    const float* y0 = (const float*)d_in[1];
    const float* W1 = (const float*)d_in[2];
    const float* b1 = (const float*)d_in[3];
    const float* W2 = (const float*)d_in[4];
    const float* b2 = (const float*)d_in[5];
    const float* W3 = (const float*)d_in[6];
    const float* b3 = (const float*)d_in[7];
    float* out = (float*)d_out;

    size_t smem_bytes = (size_t)SMEM_FLOATS * sizeof(float);
    cudaFuncSetAttribute(dde_kernel, cudaFuncAttributeMaxDynamicSharedMemorySize,
                         (int)smem_bytes);

    dde_kernel<<<NBLOCKS, NTHREADS, smem_bytes>>>(ts, y0, W1, b1, W2, b2, W3, b3,
                                                  out, (long long)out_size);
}